// round 15
// baseline (speedup 1.0000x reference)
#include <cuda_runtime.h>
#include <cuda_bf16.h>
#include <math.h>
#include <stdint.h>

// Problem constants
#define BB   16
#define TT   256
#define VV   25
#define DM   128
#define HH   8
#define HD   16
#define MAXT 300
#define SEQS (BB*VV)          // 400
#define NTOK (SEQS*TT)        // 102400
#define NBIAS (2*MAXT-1)      // 599
#define PART (HH*NTOK*HD)     // per q/k/v head-major part size (elements)
#define LOG2E 1.4426950408889634f

// GEMM tiling (bf16) — round-8 proven configuration
#define BM 128
#define BN 128
#define BK 32
#define NSTG 4
#define ASTR 40               // A row stride in halves
#define BSTR (BN + 8)         // 136 halves
#define SA (BM*ASTR)
#define SB (BK*BSTR)
#define STG (SA + SB)
#define GEMM_SMEM (NSTG*STG*2)  // 75776 bytes

// multi-pass GEMM (fixed A, streamed B)
#define MAF 136                 // fixed A row stride (halves)
#define MAFSZ (BM*MAF)          // 17408 halves
#define MSB (BK*136)            // 4352 halves per B stage
#define MP_SMEM ((MAFSZ + 4*MSB)*2)   // 69632 bytes

// weight-prep segment offsets (bf16 copies)
#define WOFF_QKV  0
#define WOFF_PROJ 49152
#define WOFF_W1   65536
#define WOFF_W2   131072
#define WTOTAL    196608
#define LNBLKS (NTOK/8)       // 12800 LN blocks
#define WBLKS  (WTOTAL/256)   // 768 wprep blocks

typedef __nv_bfloat16 bf16;

// ---------------- scratch (device globals; no runtime allocation) -------------
__device__ bf16  g_xn  [NTOK*DM];     // LN1 output
__device__ bf16  g_qkv [NTOK*3*DM];   // q/k/v, head-major [3][H][NTOK][16]
__device__ bf16  g_attn[NTOK*DM];     // attention output, head-major
__device__ float g_xf  [NTOK*DM];     // after proj + residual (fp32)
__device__ bf16  g_z   [NTOK*DM];     // LN2 output
__device__ bf16  g_h   [NTOK*4*DM];   // FFN hidden
__device__ bf16  g_w   [WTOTAL];      // bf16 weights

// ---------------- helpers ------------------------------------------------------
__device__ __forceinline__ uint32_t packbf(float lo, float hi) {
    uint32_t r;
    asm("cvt.rn.bf16x2.f32 %0, %1, %2;" : "=r"(r) : "f"(hi), "f"(lo));
    return r;
}
__device__ __forceinline__ float2 unpk(uint32_t u) {
    __nv_bfloat162 h = *reinterpret_cast<__nv_bfloat162*>(&u);
    return make_float2(__bfloat162float(h.x), __bfloat162float(h.y));
}
__device__ __forceinline__ float ex2(float x) {
    float r;
    asm("ex2.approx.ftz.f32 %0, %1;" : "=f"(r) : "f"(x));
    return r;
}
__device__ __forceinline__ void pf_l2(const void* p) {
    asm volatile("prefetch.global.L2 [%0];" :: "l"(p));
}
__device__ __forceinline__ void mma16(float* c, const uint32_t* a, const uint32_t* b) {
    asm volatile(
        "mma.sync.aligned.m16n8k16.row.col.f32.bf16.bf16.f32 "
        "{%0,%1,%2,%3}, {%4,%5,%6,%7}, {%8,%9}, {%0,%1,%2,%3};"
        : "+f"(c[0]), "+f"(c[1]), "+f"(c[2]), "+f"(c[3])
        : "r"(a[0]), "r"(a[1]), "r"(a[2]), "r"(a[3]), "r"(b[0]), "r"(b[1]));
}
__device__ __forceinline__ void ldm_x4(uint32_t* r, uint32_t addr) {
    asm volatile("ldmatrix.sync.aligned.m8n8.x4.shared.b16 {%0,%1,%2,%3}, [%4];"
        : "=r"(r[0]), "=r"(r[1]), "=r"(r[2]), "=r"(r[3]) : "r"(addr));
}
__device__ __forceinline__ void ldm_x2(uint32_t* r, uint32_t addr) {
    asm volatile("ldmatrix.sync.aligned.m8n8.x2.shared.b16 {%0,%1}, [%2];"
        : "=r"(r[0]), "=r"(r[1]) : "r"(addr));
}
__device__ __forceinline__ void ldm_x2_t(uint32_t* r, uint32_t addr) {
    asm volatile("ldmatrix.sync.aligned.m8n8.x2.trans.shared.b16 {%0,%1}, [%2];"
        : "=r"(r[0]), "=r"(r[1]) : "r"(addr));
}
__device__ __forceinline__ void cp16(uint32_t dst, const void* src) {
    asm volatile("cp.async.cg.shared.global [%0], [%1], 16;" :: "r"(dst), "l"(src));
}
__device__ __forceinline__ void cp_commit() {
    asm volatile("cp.async.commit_group;" ::: "memory");
}
template<int N>
__device__ __forceinline__ void cp_wait() {
    asm volatile("cp.async.wait_group %0;" :: "n"(N) : "memory");
}
__device__ __forceinline__ int gather_off(int row) {
    int seq = row / TT, t = row % TT;
    int b = seq / VV, v = seq % VV;
    return ((b*TT + t)*VV + v) * DM;
}

// ---------------- LN1 (gather) + weight prep, one launch ------------------------
__global__ void ln1w_kernel(const float* __restrict__ in,
                            const float* __restrict__ gw,
                            const float* __restrict__ bw,
                            bf16* __restrict__ out,
                            const float* __restrict__ qkvw,
                            const float* __restrict__ projw,
                            const float* __restrict__ w1,
                            const float* __restrict__ w2,
                            bf16* __restrict__ wdst)
{
    if (blockIdx.x >= LNBLKS) {
        int i = (blockIdx.x - LNBLKS) * 256 + threadIdx.x;
        float v;
        if      (i < WOFF_PROJ) v = qkvw[i];
        else if (i < WOFF_W1)   v = projw[i - WOFF_PROJ];
        else if (i < WOFF_W2)   v = w1[i - WOFF_W1];
        else                    v = w2[i - WOFF_W2];
        wdst[i] = __float2bfloat16(v);
        return;
    }

    int m    = (blockIdx.x * blockDim.x + threadIdx.x) >> 5;
    int lane = threadIdx.x & 31;
    int seq = m / TT, t = m % TT;
    int b = seq / VV, v = seq % VV;
    const float* src = in + ((b*TT + t)*VV + v) * DM;

    float4 x = *(const float4*)(src + lane*4);
    float s = x.x + x.y + x.z + x.w;
    #pragma unroll
    for (int o = 16; o > 0; o >>= 1) s += __shfl_xor_sync(0xffffffffu, s, o);
    float mean = s * (1.0f / DM);

    float dx0 = x.x - mean, dx1 = x.y - mean, dx2 = x.z - mean, dx3 = x.w - mean;
    float q = dx0*dx0 + dx1*dx1 + dx2*dx2 + dx3*dx3;
    #pragma unroll
    for (int o = 16; o > 0; o >>= 1) q += __shfl_xor_sync(0xffffffffu, q, o);
    float inv = rsqrtf(q * (1.0f / DM) + 1e-5f);

    float4 gv = *(const float4*)(gw + lane*4);
    float4 bv = *(const float4*)(bw + lane*4);
    uint2 r;
    r.x = packbf(dx0*inv*gv.x + bv.x, dx1*inv*gv.y + bv.y);
    r.y = packbf(dx2*inv*gv.z + bv.z, dx3*inv*gv.w + bv.w);
    *(uint2*)(out + (long)m*DM + lane*4) = r;
}

// ---------------- multi-pass GEMM: fixed A (K=128 resident), streamed B ---------
// EPI 2: gelu(+bias) -> Cb[row*NDIM+col]          (FFN1, NPASS=4)
// EPI 4: +bias -> head-major q/k/v scatter        (QKV,  NPASS=3)
template<int NPASS, int EPI>
__global__ void __launch_bounds__(256, 2)
mp_gemm(const bf16* __restrict__ A,
        const bf16* __restrict__ B,
        const float* __restrict__ bias,
        bf16* __restrict__ Cb)
{
    extern __shared__ bf16 sm[];
    uint32_t sb = (uint32_t)__cvta_generic_to_shared(sm);

    const int tid  = threadIdx.x;
    const int by   = blockIdx.x;
    const int lane = tid & 31, warp = tid >> 5;
    const int wm   = (warp & 1) * 64;
    const int wn   = (warp >> 1) * 32;
    const int g    = lane >> 2, tig = lane & 3;
    const int NDIM = NPASS * BN;
    const int NT   = 4 * NPASS;

    auto loadB = [&](int tt) {
        int pass = tt >> 2, kt = tt & 3, slot = tt & 3;
        #pragma unroll
        for (int j = 0; j < 2; j++) {
            int id = tid + j*256;
            int r = id >> 4, c8 = (id & 15) * 8;
            cp16(sb + 2*(MAFSZ + slot*MSB + r*136 + c8),
                 B + (long)(kt*BK + r)*NDIM + pass*BN + c8);
        }
    };

    // prologue: A (full 128x128) + B0 in group 0, then B1, B2
    #pragma unroll
    for (int i = 0; i < 8; i++) {
        int id = tid + i*256;
        int r = id >> 4, c8 = (id & 15) * 8;
        cp16(sb + 2*(r*MAF + c8), A + (long)(by*BM + r)*DM + c8);
    }
    loadB(0); cp_commit();
    loadB(1); cp_commit();
    loadB(2); cp_commit();

    const int a_roff = (lane & 7) + ((lane >> 3) & 1) * 8;
    const int a_coff = (lane >> 4) * 8;
    const int b_roff = lane & 15;

    float acc[4][4][4];

    #pragma unroll 1
    for (int tt = 0; tt < NT; tt++) {
        cp_wait<2>();
        __syncthreads();
        if (tt + 3 < NT) loadB(tt + 3);
        cp_commit();                 // unconditional: exact group counting

        const int pass = tt >> 2, kt = tt & 3, slot = tt & 3;
        if (kt == 0) {
            #pragma unroll
            for (int mi = 0; mi < 4; mi++)
                #pragma unroll
                for (int ni = 0; ni < 4; ni++)
                    #pragma unroll
                    for (int e = 0; e < 4; e++) acc[mi][ni][e] = 0.f;
        }

        uint32_t bbase = sb + 2*(MAFSZ + slot*MSB);
        #pragma unroll
        for (int ks = 0; ks < 2; ks++) {
            uint32_t af[4][4], bf[4][2];
            #pragma unroll
            for (int mi = 0; mi < 4; mi++)
                ldm_x4(af[mi], sb + 2*((wm + mi*16 + a_roff)*MAF
                                       + kt*BK + ks*16 + a_coff));
            #pragma unroll
            for (int ni = 0; ni < 4; ni++)
                ldm_x2_t(bf[ni], bbase + 2*((ks*16 + b_roff)*136 + wn + ni*8));
            #pragma unroll
            for (int mi = 0; mi < 4; mi++)
                #pragma unroll
                for (int ni = 0; ni < 4; ni++)
                    mma16(acc[mi][ni], af[mi], bf[ni]);
        }

        if (kt == 3) {
            #pragma unroll
            for (int mi = 0; mi < 4; mi++) {
                #pragma unroll
                for (int rr = 0; rr < 2; rr++) {
                    int row = by*BM + wm + mi*16 + rr*8 + g;
                    #pragma unroll
                    for (int ni = 0; ni < 4; ni++) {
                        int col = pass*BN + wn + ni*8 + 2*tig;
                        float vx = acc[mi][ni][rr*2 + 0] + bias[col];
                        float vy = acc[mi][ni][rr*2 + 1] + bias[col + 1];
                        if (EPI == 2) {
                            vx = 0.5f * vx * (1.0f + erff(vx * 0.70710678118654752f));
                            vy = 0.5f * vy * (1.0f + erff(vy * 0.70710678118654752f));
                            *(uint32_t*)&Cb[(long)row*NDIM + col] = packbf(vx, vy);
                        } else {   // EPI 4: head-major q/k/v
                            int part = col >> 7, rem = col & 127;
                            int hh = rem >> 4, d = rem & 15;
                            *(uint32_t*)&Cb[(long)part*PART
                                            + ((long)hh*NTOK + row)*HD + d] =
                                packbf(vx, vy);
                        }
                    }
                }
            }
        }
    }
}

// ---------------- bf16 tensor-core GEMM (round-8 proven; proj & FFN2) -----------
// EPI 1: + bias + gather(x) -> xf (Cf fp32); fused LayerNorm -> z (Cb bf16)
// EPI 3: + bias + extra[row] -> scatter fp32 out  (FFN2)
// AG 1: A is head-major [H][NTOK][16] bf16
template<int KDIM, int NDIM, int EPI, int AG>
__global__ void __launch_bounds__(256, 2)
mma_gemm(const bf16* __restrict__ A,
         const bf16* __restrict__ B,
         const float* __restrict__ bias,
         const float* __restrict__ extra,
         float* __restrict__ Cf,
         bf16* __restrict__ Cb,
         const float* __restrict__ lng,
         const float* __restrict__ lnb)
{
    extern __shared__ bf16 smem[];
    uint32_t sbase = (uint32_t)__cvta_generic_to_shared(smem);

    const int tid  = threadIdx.x;
    const int bx   = blockIdx.x, by = blockIdx.y;
    const int lane = tid & 31, warp = tid >> 5;
    const int wm   = (warp & 1) * 64;
    const int wn   = (warp >> 1) * 32;
    const int g    = lane >> 2, tig = lane & 3;

    const int NK = KDIM / BK;
    float acc[4][4][4] = {};

    auto load_tile = [&](int kt, int slot) {
        uint32_t sb = sbase + 2*(slot*STG);
        #pragma unroll
        for (int i = 0; i < 2; i++) {
            int id = tid + i*256;
            int r = id >> 2, c8 = (id & 3) * 8;
            uint32_t dst = sb + 2*(r*ASTR + c8);
            int row = by*BM + r;
            if (AG) {
                int k = kt*BK + c8;
                cp16(dst, A + ((long)((k >> 4)*NTOK + row))*HD + (k & 15));
            } else {
                cp16(dst, A + (long)row*KDIM + kt*BK + c8);
            }
        }
        #pragma unroll
        for (int j = 0; j < 2; j++) {
            int id = tid + j*256;
            int r = id >> 4, c8 = (id & 15) * 8;
            uint32_t dst = sb + 2*(SA + r*BSTR + c8);
            cp16(dst, B + (long)(kt*BK + r)*NDIM + bx*BN + c8);
        }
    };

    #pragma unroll
    for (int s = 0; s < NSTG-1; s++) {
        if (s < NK) load_tile(s, s);
        cp_commit();
    }

    // L2 prefetch of epilogue operands (x for EPI1, xf for EPI3):
    // one 128B line per accumulator row covers this thread's 32-col range.
    if (EPI == 1 || EPI == 3) {
        #pragma unroll
        for (int mi = 0; mi < 4; mi++)
            #pragma unroll
            for (int rr = 0; rr < 2; rr++) {
                int row = by*BM + wm + mi*16 + rr*8 + g;
                const float* p = (EPI == 1)
                    ? (extra + gather_off(row) + wn)
                    : (extra + (long)row*DM + wn);
                pf_l2(p);
            }
    }

    const int a_roff = (lane & 7) + ((lane >> 3) & 1) * 8;
    const int a_coff = (lane >> 4) * 8;
    const int b_roff = lane & 15;

    #pragma unroll 1
    for (int kt = 0; kt < NK; kt++) {
        cp_wait<NSTG-2>();
        __syncthreads();
        int lt = kt + NSTG - 1;
        if (lt < NK) load_tile(lt, lt & (NSTG-1));
        cp_commit();

        uint32_t abase = sbase + 2*((kt & (NSTG-1))*STG);
        uint32_t bbase = abase + 2*SA;

        #pragma unroll
        for (int ks = 0; ks < 2; ks++) {
            uint32_t af[4][4], bf[4][2];
            #pragma unroll
            for (int mi = 0; mi < 4; mi++)
                ldm_x4(af[mi], abase + 2*((wm + mi*16 + a_roff)*ASTR + ks*16 + a_coff));
            #pragma unroll
            for (int ni = 0; ni < 4; ni++)
                ldm_x2_t(bf[ni], bbase + 2*((ks*16 + b_roff)*BSTR + wn + ni*8));
            #pragma unroll
            for (int mi = 0; mi < 4; mi++)
                #pragma unroll
                for (int ni = 0; ni < 4; ni++)
                    mma16(acc[mi][ni], af[mi], bf[ni]);
        }
    }

    // ---------------- epilogue ----------------
    if (EPI == 1) {
        __syncthreads();
        float* red = (float*)smem;
        const int wngrp = warp >> 1;

        float rsum[4][2], rsq[4][2];
        #pragma unroll
        for (int mi = 0; mi < 4; mi++) {
            #pragma unroll
            for (int rr = 0; rr < 2; rr++) {
                int rloc = wm + mi*16 + rr*8 + g;
                int row  = by*BM + rloc;
                int go   = gather_off(row);
                float ls = 0.f, lq = 0.f;
                #pragma unroll
                for (int ni = 0; ni < 4; ni++) {
                    int col = wn + ni*8 + 2*tig;
                    float vx = acc[mi][ni][rr*2+0] + bias[col]   + extra[go + col];
                    float vy = acc[mi][ni][rr*2+1] + bias[col+1] + extra[go + col + 1];
                    acc[mi][ni][rr*2+0] = vx;
                    acc[mi][ni][rr*2+1] = vy;
                    float2 r = {vx, vy};
                    *(float2*)&Cf[(long)row*DM + col] = r;
                    ls += vx + vy;
                    lq += vx*vx + vy*vy;
                }
                rsum[mi][rr] = ls; rsq[mi][rr] = lq;
            }
        }
        #pragma unroll
        for (int mi = 0; mi < 4; mi++)
            #pragma unroll
            for (int rr = 0; rr < 2; rr++) {
                #pragma unroll
                for (int o = 1; o <= 2; o <<= 1) {
                    rsum[mi][rr] += __shfl_xor_sync(0xffffffffu, rsum[mi][rr], o);
                    rsq[mi][rr]  += __shfl_xor_sync(0xffffffffu, rsq[mi][rr],  o);
                }
            }
        if (tig == 0) {
            #pragma unroll
            for (int mi = 0; mi < 4; mi++)
                #pragma unroll
                for (int rr = 0; rr < 2; rr++) {
                    int rloc = wm + mi*16 + rr*8 + g;
                    red[(rloc*4 + wngrp)*2 + 0] = rsum[mi][rr];
                    red[(rloc*4 + wngrp)*2 + 1] = rsq[mi][rr];
                }
        }
        __syncthreads();
        #pragma unroll
        for (int mi = 0; mi < 4; mi++) {
            #pragma unroll
            for (int rr = 0; rr < 2; rr++) {
                int rloc = wm + mi*16 + rr*8 + g;
                int row  = by*BM + rloc;
                float s = 0.f, q = 0.f;
                #pragma unroll
                for (int w2 = 0; w2 < 4; w2++) {
                    s += red[(rloc*4 + w2)*2 + 0];
                    q += red[(rloc*4 + w2)*2 + 1];
                }
                float mean = s * (1.0f/DM);
                float var  = q * (1.0f/DM) - mean*mean;
                float inv  = rsqrtf(var + 1e-5f);
                #pragma unroll
                for (int ni = 0; ni < 4; ni++) {
                    int col = wn + ni*8 + 2*tig;
                    float zx = (acc[mi][ni][rr*2+0] - mean)*inv*lng[col]   + lnb[col];
                    float zy = (acc[mi][ni][rr*2+1] - mean)*inv*lng[col+1] + lnb[col+1];
                    *(uint32_t*)&Cb[(long)row*DM + col] = packbf(zx, zy);
                }
            }
        }
        return;
    }

    // EPI 3
    #pragma unroll
    for (int mi = 0; mi < 4; mi++) {
        #pragma unroll
        for (int rr = 0; rr < 2; rr++) {
            int row = by*BM + wm + mi*16 + rr*8 + g;
            int go  = gather_off(row);
            #pragma unroll
            for (int ni = 0; ni < 4; ni++) {
                int col = bx*BN + wn + ni*8 + 2*tig;
                float vx = acc[mi][ni][rr*2 + 0] + bias[col]
                         + extra[(long)row*DM + col];
                float vy = acc[mi][ni][rr*2 + 1] + bias[col + 1]
                         + extra[(long)row*DM + col + 1];
                float2 r = {vx, vy};
                *(float2*)&Cf[go + col] = r;
            }
        }
    }
}

// ---------------- bf16 tensor-core attention (round-13, head-major out) ---------
__global__ void __launch_bounds__(256, 4)
attn_bf16_kernel(const bf16* __restrict__ qkv,
                 const float* __restrict__ logit_scale,
                 const float* __restrict__ rpb,
                 bf16* __restrict__ out)
{
    __shared__ __align__(16) bf16 Qs[TT*24];
    __shared__ __align__(16) bf16 Ks[TT*24];
    __shared__ __align__(16) bf16 Vs[TT*24];
    __shared__ float bs[NBIAS + 1];

    const int seq = blockIdx.x, h = blockIdx.y;
    const int t    = threadIdx.x;
    const int lane = t & 31, w = t >> 5;
    const int g    = lane >> 2, tig = lane & 3;

    for (int i = t; i < NBIAS; i += 256) bs[i] = rpb[h*NBIAS + i] * LOG2E;

    const long idx = ((long)h*NTOK + seq*TT + t) * HD;
    const float scale = __expf(fminf(logit_scale[h], 4.6051701859880914f));

    {
        uint4 qu0 = *(const uint4*)(qkv + idx);
        uint4 qu1 = *(const uint4*)(qkv + idx + 8);
        uint4 ku0 = *(const uint4*)(qkv + PART + idx);
        uint4 ku1 = *(const uint4*)(qkv + PART + idx + 8);
        uint4 vu0 = *(const uint4*)(qkv + 2L*PART + idx);
        uint4 vu1 = *(const uint4*)(qkv + 2L*PART + idx + 8);

        uint32_t uq[8] = {qu0.x,qu0.y,qu0.z,qu0.w, qu1.x,qu1.y,qu1.z,qu1.w};
        uint32_t uk[8] = {ku0.x,ku0.y,ku0.z,ku0.w, ku1.x,ku1.y,ku1.z,ku1.w};
        float q[16], k[16];
        float qs = 0.f, ks = 0.f;
        #pragma unroll
        for (int j = 0; j < 8; j++) {
            float2 fq = unpk(uq[j]), fk = unpk(uk[j]);
            q[2*j] = fq.x; q[2*j+1] = fq.y;
            k[2*j] = fk.x; k[2*j+1] = fk.y;
            qs += fq.x*fq.x + fq.y*fq.y;
            ks += fk.x*fk.x + fk.y*fk.y;
        }
        float qf = scale * 0.25f * LOG2E / fmaxf(sqrtf(qs), 1e-12f);
        float kf = 1.0f / fmaxf(sqrtf(ks), 1e-12f);
        uint32_t wq[8], wk[8];
        #pragma unroll
        for (int j = 0; j < 8; j++) {
            wq[j] = packbf(q[2*j]*qf, q[2*j+1]*qf);
            wk[j] = packbf(k[2*j]*kf, k[2*j+1]*kf);
        }
        *(uint4*)&Qs[t*24]     = make_uint4(wq[0],wq[1],wq[2],wq[3]);
        *(uint4*)&Qs[t*24 + 8] = make_uint4(wq[4],wq[5],wq[6],wq[7]);
        *(uint4*)&Ks[t*24]     = make_uint4(wk[0],wk[1],wk[2],wk[3]);
        *(uint4*)&Ks[t*24 + 8] = make_uint4(wk[4],wk[5],wk[6],wk[7]);
        *(uint4*)&Vs[t*24]      = vu0;
        *(uint4*)&Vs[t*24 + 8]  = vu1;
        *(uint4*)&Vs[t*24 + 16] = make_uint4(0x00003F80u, 0u, 0u, 0u);  // ones col
    }
    __syncthreads();

    uint32_t sQ = (uint32_t)__cvta_generic_to_shared(Qs);
    uint32_t sK = (uint32_t)__cvta_generic_to_shared(Ks);
    uint32_t sV = (uint32_t)__cvta_generic_to_shared(Vs);

    const int m0 = w * 32;
    const int fr = (lane & 7) + ((lane >> 3) & 1) * 8;
    const int fc = (lane >> 4) * 8;

    uint32_t qa[2][4];
    #pragma unroll
    for (int mi = 0; mi < 2; mi++)
        ldm_x4(qa[mi], sQ + 2*((m0 + mi*16 + fr)*24 + fc));

    float oacc[2][3][4] = {};

    #pragma unroll 1
    for (int cc = 0; cc < 8; cc++) {
        const int s0 = cc * 32;
        float sacc[2][4][4];

        #pragma unroll
        for (int mi = 0; mi < 2; mi++)
            #pragma unroll
            for (int ni = 0; ni < 4; ni++) {
                int d = m0 + mi*16 + g - (s0 + ni*8 + 2*tig) + (MAXT-1);
                sacc[mi][ni][0] = bs[d];
                sacc[mi][ni][1] = bs[d-1];
                sacc[mi][ni][2] = bs[d+8];
                sacc[mi][ni][3] = bs[d+7];
            }

        #pragma unroll
        for (int ni = 0; ni < 4; ni++) {
            uint32_t kb[2];
            ldm_x2(kb, sK + 2*((s0 + ni*8 + (lane & 7))*24 + ((lane >> 3) & 1)*8));
            #pragma unroll
            for (int mi = 0; mi < 2; mi++)
                mma16(sacc[mi][ni], qa[mi], kb);
        }

        #pragma unroll
        for (int mi = 0; mi < 2; mi++)
            #pragma unroll
            for (int ni = 0; ni < 4; ni++) {
                sacc[mi][ni][0] = ex2(sacc[mi][ni][0]);
                sacc[mi][ni][1] = ex2(sacc[mi][ni][1]);
                sacc[mi][ni][2] = ex2(sacc[mi][ni][2]);
                sacc[mi][ni][3] = ex2(sacc[mi][ni][3]);
            }

        #pragma unroll
        for (int kk = 0; kk < 2; kk++) {
            uint32_t pa[2][4];
            #pragma unroll
            for (int mi = 0; mi < 2; mi++) {
                pa[mi][0] = packbf(sacc[mi][2*kk  ][0], sacc[mi][2*kk  ][1]);
                pa[mi][1] = packbf(sacc[mi][2*kk  ][2], sacc[mi][2*kk  ][3]);
                pa[mi][2] = packbf(sacc[mi][2*kk+1][0], sacc[mi][2*kk+1][1]);
                pa[mi][3] = packbf(sacc[mi][2*kk+1][2], sacc[mi][2*kk+1][3]);
            }
            #pragma unroll
            for (int nd = 0; nd < 3; nd++) {
                uint32_t vb[2];
                ldm_x2_t(vb, sV + 2*((s0 + kk*16 + (lane & 15))*24 + nd*8));
                #pragma unroll
                for (int mi = 0; mi < 2; mi++)
                    mma16(oacc[mi][nd], pa[mi], vb);
            }
        }
    }

    #pragma unroll
    for (int mi = 0; mi < 2; mi++) {
        #pragma unroll
        for (int rr = 0; rr < 2; rr++) {
            float l = __shfl_sync(0xffffffffu, oacc[mi][2][rr*2], lane & ~3);
            float il = 1.0f / l;
            int row = m0 + mi*16 + rr*8 + g;
            long oidx = ((long)h*NTOK + seq*TT + row) * HD;
            #pragma unroll
            for (int nd = 0; nd < 2; nd++) {
                *(uint32_t*)&out[oidx + nd*8 + 2*tig] =
                    packbf(oacc[mi][nd][rr*2+0]*il, oacc[mi][nd][rr*2+1]*il);
            }
        }
    }
}

// -------------------------------- launch ----------------------------------------
extern "C" void kernel_launch(void* const* d_in, const int* in_sizes, int n_in,
                              void* d_out, int out_size)
{
    const float* x     = (const float*)d_in[0];
    const float* ln1g  = (const float*)d_in[1];
    const float* ln1b  = (const float*)d_in[2];
    const float* qkvw  = (const float*)d_in[3];
    const float* qkvb  = (const float*)d_in[4];
    const float* projw = (const float*)d_in[5];
    const float* projb = (const float*)d_in[6];
    const float* ls    = (const float*)d_in[7];
    const float* rpb   = (const float*)d_in[8];
    const float* ln2g  = (const float*)d_in[9];
    const float* ln2b  = (const float*)d_in[10];
    const float* w1    = (const float*)d_in[11];
    const float* b1    = (const float*)d_in[12];
    const float* w2    = (const float*)d_in[13];
    const float* b2    = (const float*)d_in[14];
    float* out = (float*)d_out;

    bf16 *xn, *qkv, *attn, *z, *hb, *wbuf;
    float *xf;
    cudaGetSymbolAddress((void**)&xn,   g_xn);
    cudaGetSymbolAddress((void**)&qkv,  g_qkv);
    cudaGetSymbolAddress((void**)&attn, g_attn);
    cudaGetSymbolAddress((void**)&xf,   g_xf);
    cudaGetSymbolAddress((void**)&z,    g_z);
    cudaGetSymbolAddress((void**)&hb,   g_h);
    cudaGetSymbolAddress((void**)&wbuf, g_w);

    cudaFuncSetAttribute(mp_gemm<3, 4>, cudaFuncAttributeMaxDynamicSharedMemorySize, MP_SMEM);
    cudaFuncSetAttribute(mp_gemm<4, 2>, cudaFuncAttributeMaxDynamicSharedMemorySize, MP_SMEM);
    cudaFuncSetAttribute(mma_gemm<128, 128, 1, 1>, cudaFuncAttributeMaxDynamicSharedMemorySize, GEMM_SMEM);
    cudaFuncSetAttribute(mma_gemm<512, 128, 3, 0>, cudaFuncAttributeMaxDynamicSharedMemorySize, GEMM_SMEM);

    // 0+1) LN1 (gather) + weight prep in one launch
    ln1w_kernel<<<LNBLKS + WBLKS, 256>>>(x, ln1g, ln1b, xn,
                                         qkvw, projw, w1, w2, wbuf);
    // 2) QKV projection (fixed A, 3 N-passes) -> head-major bf16 q/k/v
    mp_gemm<3, 4><<<NTOK/BM, 256, MP_SMEM>>>(xn, wbuf + WOFF_QKV, qkvb, qkv);
    // 3) bf16 tensor-core attention -> head-major attn
    attn_bf16_kernel<<<dim3(SEQS, HH), 256>>>(qkv, ls, rpb, attn);
    // 4) proj + residual -> xf (fp32), fused LN2 -> z (bf16); x prefetched to L2
    mma_gemm<128, 128, 1, 1><<<dim3(1, NTOK/BM), 256, GEMM_SMEM>>>(
        attn, wbuf + WOFF_PROJ, projb, x, xf, z, ln2g, ln2b);
    // 5) FFN1 + exact GELU (fixed A, 4 N-passes) -> h (bf16)
    mp_gemm<4, 2><<<NTOK/BM, 256, MP_SMEM>>>(z, wbuf + WOFF_W1, b1, hb);
    // 6) FFN2 + residual -> scatter fp32 (B,T,V,D) output; xf prefetched to L2
    mma_gemm<512, 128, 3, 0><<<dim3(1, NTOK/BM), 256, GEMM_SMEM>>>(
        hb, wbuf + WOFF_W2, b2, xf, out, nullptr, nullptr, nullptr);
}

// round 16
// speedup vs baseline: 1.0481x; 1.0481x over previous
#include <cuda_runtime.h>
#include <cuda_bf16.h>
#include <math.h>
#include <stdint.h>

// Problem constants
#define BB   16
#define TT   256
#define VV   25
#define DM   128
#define HH   8
#define HD   16
#define MAXT 300
#define SEQS (BB*VV)          // 400
#define NTOK (SEQS*TT)        // 102400
#define NBIAS (2*MAXT-1)      // 599
#define PART (HH*NTOK*HD)     // per q/k/v head-major part size (elements)
#define LOG2E 1.4426950408889634f

// GEMM tiling (bf16) — round-8 proven configuration
#define BM 128
#define BN 128
#define BK 32
#define NSTG 4
#define ASTR 40               // A row stride in halves
#define BSTR (BN + 8)         // 136 halves
#define SA (BM*ASTR)
#define SB (BK*BSTR)
#define STG (SA + SB)
#define GEMM_SMEM (NSTG*STG*2)  // 75776 bytes

// multi-pass GEMM (fixed A, streamed B)
#define MAF 136                 // fixed A row stride (halves)
#define MAFSZ (BM*MAF)          // 17408 halves
#define MSB (BK*136)            // 4352 halves per B stage
#define MP_SMEM ((MAFSZ + 4*MSB)*2)   // 69632 bytes

// weight-prep segment offsets (bf16 copies)
#define WOFF_QKV  0
#define WOFF_PROJ 49152
#define WOFF_W1   65536
#define WOFF_W2   131072
#define WTOTAL    196608
#define LNBLKS (NTOK/8)       // 12800 LN blocks
#define WBLKS  (WTOTAL/256)   // 768 wprep blocks

typedef __nv_bfloat16 bf16;

// ---------------- scratch (device globals; no runtime allocation) -------------
__device__ bf16  g_xn  [NTOK*DM];     // LN1 output
__device__ bf16  g_qkv [NTOK*3*DM];   // q/k/v, head-major [3][H][NTOK][16]
__device__ bf16  g_attn[NTOK*DM];     // attention output, head-major
__device__ float g_xf  [NTOK*DM];     // after proj + residual (fp32)
__device__ bf16  g_z   [NTOK*DM];     // LN2 output
__device__ bf16  g_h   [NTOK*4*DM];   // FFN hidden
__device__ bf16  g_w   [WTOTAL];      // bf16 weights

// ---------------- helpers ------------------------------------------------------
__device__ __forceinline__ uint32_t packbf(float lo, float hi) {
    uint32_t r;
    asm("cvt.rn.bf16x2.f32 %0, %1, %2;" : "=r"(r) : "f"(hi), "f"(lo));
    return r;
}
__device__ __forceinline__ float2 unpk(uint32_t u) {
    __nv_bfloat162 h = *reinterpret_cast<__nv_bfloat162*>(&u);
    return make_float2(__bfloat162float(h.x), __bfloat162float(h.y));
}
__device__ __forceinline__ float ex2(float x) {
    float r;
    asm("ex2.approx.ftz.f32 %0, %1;" : "=f"(r) : "f"(x));
    return r;
}
__device__ __forceinline__ void mma16(float* c, const uint32_t* a, const uint32_t* b) {
    asm volatile(
        "mma.sync.aligned.m16n8k16.row.col.f32.bf16.bf16.f32 "
        "{%0,%1,%2,%3}, {%4,%5,%6,%7}, {%8,%9}, {%0,%1,%2,%3};"
        : "+f"(c[0]), "+f"(c[1]), "+f"(c[2]), "+f"(c[3])
        : "r"(a[0]), "r"(a[1]), "r"(a[2]), "r"(a[3]), "r"(b[0]), "r"(b[1]));
}
__device__ __forceinline__ void ldm_x4(uint32_t* r, uint32_t addr) {
    asm volatile("ldmatrix.sync.aligned.m8n8.x4.shared.b16 {%0,%1,%2,%3}, [%4];"
        : "=r"(r[0]), "=r"(r[1]), "=r"(r[2]), "=r"(r[3]) : "r"(addr));
}
__device__ __forceinline__ void ldm_x2(uint32_t* r, uint32_t addr) {
    asm volatile("ldmatrix.sync.aligned.m8n8.x2.shared.b16 {%0,%1}, [%2];"
        : "=r"(r[0]), "=r"(r[1]) : "r"(addr));
}
__device__ __forceinline__ void ldm_x2_t(uint32_t* r, uint32_t addr) {
    asm volatile("ldmatrix.sync.aligned.m8n8.x2.trans.shared.b16 {%0,%1}, [%2];"
        : "=r"(r[0]), "=r"(r[1]) : "r"(addr));
}
__device__ __forceinline__ void cp16(uint32_t dst, const void* src) {
    asm volatile("cp.async.cg.shared.global [%0], [%1], 16;" :: "r"(dst), "l"(src));
}
__device__ __forceinline__ void cp_commit() {
    asm volatile("cp.async.commit_group;" ::: "memory");
}
template<int N>
__device__ __forceinline__ void cp_wait() {
    asm volatile("cp.async.wait_group %0;" :: "n"(N) : "memory");
}
__device__ __forceinline__ int gather_off(int row) {
    int seq = row / TT, t = row % TT;
    int b = seq / VV, v = seq % VV;
    return ((b*TT + t)*VV + v) * DM;
}

// ---------------- LN1 (gather) + weight prep, one launch ------------------------
__global__ void ln1w_kernel(const float* __restrict__ in,
                            const float* __restrict__ gw,
                            const float* __restrict__ bw,
                            bf16* __restrict__ out,
                            const float* __restrict__ qkvw,
                            const float* __restrict__ projw,
                            const float* __restrict__ w1,
                            const float* __restrict__ w2,
                            bf16* __restrict__ wdst)
{
    if (blockIdx.x >= LNBLKS) {
        int i = (blockIdx.x - LNBLKS) * 256 + threadIdx.x;
        float v;
        if      (i < WOFF_PROJ) v = qkvw[i];
        else if (i < WOFF_W1)   v = projw[i - WOFF_PROJ];
        else if (i < WOFF_W2)   v = w1[i - WOFF_W1];
        else                    v = w2[i - WOFF_W2];
        wdst[i] = __float2bfloat16(v);
        return;
    }

    int m    = (blockIdx.x * blockDim.x + threadIdx.x) >> 5;
    int lane = threadIdx.x & 31;
    int seq = m / TT, t = m % TT;
    int b = seq / VV, v = seq % VV;
    const float* src = in + ((b*TT + t)*VV + v) * DM;

    float4 x = *(const float4*)(src + lane*4);
    float s = x.x + x.y + x.z + x.w;
    #pragma unroll
    for (int o = 16; o > 0; o >>= 1) s += __shfl_xor_sync(0xffffffffu, s, o);
    float mean = s * (1.0f / DM);

    float dx0 = x.x - mean, dx1 = x.y - mean, dx2 = x.z - mean, dx3 = x.w - mean;
    float q = dx0*dx0 + dx1*dx1 + dx2*dx2 + dx3*dx3;
    #pragma unroll
    for (int o = 16; o > 0; o >>= 1) q += __shfl_xor_sync(0xffffffffu, q, o);
    float inv = rsqrtf(q * (1.0f / DM) + 1e-5f);

    float4 gv = *(const float4*)(gw + lane*4);
    float4 bv = *(const float4*)(bw + lane*4);
    uint2 r;
    r.x = packbf(dx0*inv*gv.x + bv.x, dx1*inv*gv.y + bv.y);
    r.y = packbf(dx2*inv*gv.z + bv.z, dx3*inv*gv.w + bv.w);
    *(uint2*)(out + (long)m*DM + lane*4) = r;
}

// ---------------- multi-pass GEMM: fixed A (K=128 resident), streamed B ---------
// EPI 2: gelu(+bias) -> Cb[row*NDIM+col]          (FFN1, NPASS=4)
// EPI 4: +bias -> head-major q/k/v scatter        (QKV,  NPASS=3)
template<int NPASS, int EPI>
__global__ void __launch_bounds__(256, 2)
mp_gemm(const bf16* __restrict__ A,
        const bf16* __restrict__ B,
        const float* __restrict__ bias,
        bf16* __restrict__ Cb)
{
    extern __shared__ bf16 sm[];
    uint32_t sb = (uint32_t)__cvta_generic_to_shared(sm);

    const int tid  = threadIdx.x;
    const int by   = blockIdx.x;
    const int lane = tid & 31, warp = tid >> 5;
    const int wm   = (warp & 1) * 64;
    const int wn   = (warp >> 1) * 32;
    const int g    = lane >> 2, tig = lane & 3;
    const int NDIM = NPASS * BN;
    const int NT   = 4 * NPASS;

    auto loadB = [&](int tt) {
        int pass = tt >> 2, kt = tt & 3, slot = tt & 3;
        #pragma unroll
        for (int j = 0; j < 2; j++) {
            int id = tid + j*256;
            int r = id >> 4, c8 = (id & 15) * 8;
            cp16(sb + 2*(MAFSZ + slot*MSB + r*136 + c8),
                 B + (long)(kt*BK + r)*NDIM + pass*BN + c8);
        }
    };

    // prologue: A (full 128x128) + B0 in group 0, then B1, B2
    #pragma unroll
    for (int i = 0; i < 8; i++) {
        int id = tid + i*256;
        int r = id >> 4, c8 = (id & 15) * 8;
        cp16(sb + 2*(r*MAF + c8), A + (long)(by*BM + r)*DM + c8);
    }
    loadB(0); cp_commit();
    loadB(1); cp_commit();
    loadB(2); cp_commit();

    const int a_roff = (lane & 7) + ((lane >> 3) & 1) * 8;
    const int a_coff = (lane >> 4) * 8;
    const int b_roff = lane & 15;

    float acc[4][4][4];

    #pragma unroll 1
    for (int tt = 0; tt < NT; tt++) {
        cp_wait<2>();
        __syncthreads();
        if (tt + 3 < NT) loadB(tt + 3);
        cp_commit();                 // unconditional: exact group counting

        const int pass = tt >> 2, kt = tt & 3, slot = tt & 3;
        if (kt == 0) {
            #pragma unroll
            for (int mi = 0; mi < 4; mi++)
                #pragma unroll
                for (int ni = 0; ni < 4; ni++)
                    #pragma unroll
                    for (int e = 0; e < 4; e++) acc[mi][ni][e] = 0.f;
        }

        uint32_t bbase = sb + 2*(MAFSZ + slot*MSB);
        #pragma unroll
        for (int ks = 0; ks < 2; ks++) {
            uint32_t af[4][4], bf[4][2];
            #pragma unroll
            for (int mi = 0; mi < 4; mi++)
                ldm_x4(af[mi], sb + 2*((wm + mi*16 + a_roff)*MAF
                                       + kt*BK + ks*16 + a_coff));
            #pragma unroll
            for (int ni = 0; ni < 4; ni++)
                ldm_x2_t(bf[ni], bbase + 2*((ks*16 + b_roff)*136 + wn + ni*8));
            #pragma unroll
            for (int mi = 0; mi < 4; mi++)
                #pragma unroll
                for (int ni = 0; ni < 4; ni++)
                    mma16(acc[mi][ni], af[mi], bf[ni]);
        }

        if (kt == 3) {
            #pragma unroll
            for (int mi = 0; mi < 4; mi++) {
                #pragma unroll
                for (int rr = 0; rr < 2; rr++) {
                    int row = by*BM + wm + mi*16 + rr*8 + g;
                    #pragma unroll
                    for (int ni = 0; ni < 4; ni++) {
                        int col = pass*BN + wn + ni*8 + 2*tig;
                        float vx = acc[mi][ni][rr*2 + 0] + bias[col];
                        float vy = acc[mi][ni][rr*2 + 1] + bias[col + 1];
                        if (EPI == 2) {
                            vx = 0.5f * vx * (1.0f + erff(vx * 0.70710678118654752f));
                            vy = 0.5f * vy * (1.0f + erff(vy * 0.70710678118654752f));
                            *(uint32_t*)&Cb[(long)row*NDIM + col] = packbf(vx, vy);
                        } else {   // EPI 4: head-major q/k/v
                            int part = col >> 7, rem = col & 127;
                            int hh = rem >> 4, d = rem & 15;
                            *(uint32_t*)&Cb[(long)part*PART
                                            + ((long)hh*NTOK + row)*HD + d] =
                                packbf(vx, vy);
                        }
                    }
                }
            }
        }
    }
}

// ---------------- bf16 tensor-core GEMM (round-8 proven; proj & FFN2) -----------
// EPI 1: + bias + gather(x) -> xf (Cf fp32); fused LayerNorm -> z (Cb bf16)
// EPI 3: + bias + extra[row] -> scatter fp32 out  (FFN2)
// AG 1: A is head-major [H][NTOK][16] bf16
template<int KDIM, int NDIM, int EPI, int AG>
__global__ void __launch_bounds__(256, 2)
mma_gemm(const bf16* __restrict__ A,
         const bf16* __restrict__ B,
         const float* __restrict__ bias,
         const float* __restrict__ extra,
         float* __restrict__ Cf,
         bf16* __restrict__ Cb,
         const float* __restrict__ lng,
         const float* __restrict__ lnb)
{
    extern __shared__ bf16 smem[];
    uint32_t sbase = (uint32_t)__cvta_generic_to_shared(smem);

    const int tid  = threadIdx.x;
    const int bx   = blockIdx.x, by = blockIdx.y;
    const int lane = tid & 31, warp = tid >> 5;
    const int wm   = (warp & 1) * 64;
    const int wn   = (warp >> 1) * 32;
    const int g    = lane >> 2, tig = lane & 3;

    const int NK = KDIM / BK;
    float acc[4][4][4] = {};

    auto load_tile = [&](int kt, int slot) {
        uint32_t sb = sbase + 2*(slot*STG);
        #pragma unroll
        for (int i = 0; i < 2; i++) {
            int id = tid + i*256;
            int r = id >> 2, c8 = (id & 3) * 8;
            uint32_t dst = sb + 2*(r*ASTR + c8);
            int row = by*BM + r;
            if (AG) {
                int k = kt*BK + c8;
                cp16(dst, A + ((long)((k >> 4)*NTOK + row))*HD + (k & 15));
            } else {
                cp16(dst, A + (long)row*KDIM + kt*BK + c8);
            }
        }
        #pragma unroll
        for (int j = 0; j < 2; j++) {
            int id = tid + j*256;
            int r = id >> 4, c8 = (id & 15) * 8;
            uint32_t dst = sb + 2*(SA + r*BSTR + c8);
            cp16(dst, B + (long)(kt*BK + r)*NDIM + bx*BN + c8);
        }
    };

    #pragma unroll
    for (int s = 0; s < NSTG-1; s++) {
        if (s < NK) load_tile(s, s);
        cp_commit();
    }

    const int a_roff = (lane & 7) + ((lane >> 3) & 1) * 8;
    const int a_coff = (lane >> 4) * 8;
    const int b_roff = lane & 15;

    #pragma unroll 1
    for (int kt = 0; kt < NK; kt++) {
        cp_wait<NSTG-2>();
        __syncthreads();
        int lt = kt + NSTG - 1;
        if (lt < NK) load_tile(lt, lt & (NSTG-1));
        cp_commit();

        uint32_t abase = sbase + 2*((kt & (NSTG-1))*STG);
        uint32_t bbase = abase + 2*SA;

        #pragma unroll
        for (int ks = 0; ks < 2; ks++) {
            uint32_t af[4][4], bf[4][2];
            #pragma unroll
            for (int mi = 0; mi < 4; mi++)
                ldm_x4(af[mi], abase + 2*((wm + mi*16 + a_roff)*ASTR + ks*16 + a_coff));
            #pragma unroll
            for (int ni = 0; ni < 4; ni++)
                ldm_x2_t(bf[ni], bbase + 2*((ks*16 + b_roff)*BSTR + wn + ni*8));
            #pragma unroll
            for (int mi = 0; mi < 4; mi++)
                #pragma unroll
                for (int ni = 0; ni < 4; ni++)
                    mma16(acc[mi][ni], af[mi], bf[ni]);
        }
    }

    // ---------------- epilogue ----------------
    if (EPI == 1) {
        __syncthreads();
        float* red = (float*)smem;
        const int wngrp = warp >> 1;

        float rsum[4][2], rsq[4][2];
        #pragma unroll
        for (int mi = 0; mi < 4; mi++) {
            #pragma unroll
            for (int rr = 0; rr < 2; rr++) {
                int rloc = wm + mi*16 + rr*8 + g;
                int row  = by*BM + rloc;
                int go   = gather_off(row);
                float ls = 0.f, lq = 0.f;
                #pragma unroll
                for (int ni = 0; ni < 4; ni++) {
                    int col = wn + ni*8 + 2*tig;
                    float vx = acc[mi][ni][rr*2+0] + bias[col]   + extra[go + col];
                    float vy = acc[mi][ni][rr*2+1] + bias[col+1] + extra[go + col + 1];
                    acc[mi][ni][rr*2+0] = vx;
                    acc[mi][ni][rr*2+1] = vy;
                    float2 r = {vx, vy};
                    *(float2*)&Cf[(long)row*DM + col] = r;
                    ls += vx + vy;
                    lq += vx*vx + vy*vy;
                }
                rsum[mi][rr] = ls; rsq[mi][rr] = lq;
            }
        }
        #pragma unroll
        for (int mi = 0; mi < 4; mi++)
            #pragma unroll
            for (int rr = 0; rr < 2; rr++) {
                #pragma unroll
                for (int o = 1; o <= 2; o <<= 1) {
                    rsum[mi][rr] += __shfl_xor_sync(0xffffffffu, rsum[mi][rr], o);
                    rsq[mi][rr]  += __shfl_xor_sync(0xffffffffu, rsq[mi][rr],  o);
                }
            }
        if (tig == 0) {
            #pragma unroll
            for (int mi = 0; mi < 4; mi++)
                #pragma unroll
                for (int rr = 0; rr < 2; rr++) {
                    int rloc = wm + mi*16 + rr*8 + g;
                    red[(rloc*4 + wngrp)*2 + 0] = rsum[mi][rr];
                    red[(rloc*4 + wngrp)*2 + 1] = rsq[mi][rr];
                }
        }
        __syncthreads();
        #pragma unroll
        for (int mi = 0; mi < 4; mi++) {
            #pragma unroll
            for (int rr = 0; rr < 2; rr++) {
                int rloc = wm + mi*16 + rr*8 + g;
                int row  = by*BM + rloc;
                float s = 0.f, q = 0.f;
                #pragma unroll
                for (int w2 = 0; w2 < 4; w2++) {
                    s += red[(rloc*4 + w2)*2 + 0];
                    q += red[(rloc*4 + w2)*2 + 1];
                }
                float mean = s * (1.0f/DM);
                float var  = q * (1.0f/DM) - mean*mean;
                float inv  = rsqrtf(var + 1e-5f);
                #pragma unroll
                for (int ni = 0; ni < 4; ni++) {
                    int col = wn + ni*8 + 2*tig;
                    float zx = (acc[mi][ni][rr*2+0] - mean)*inv*lng[col]   + lnb[col];
                    float zy = (acc[mi][ni][rr*2+1] - mean)*inv*lng[col+1] + lnb[col+1];
                    *(uint32_t*)&Cb[(long)row*DM + col] = packbf(zx, zy);
                }
            }
        }
        return;
    }

    // EPI 3
    #pragma unroll
    for (int mi = 0; mi < 4; mi++) {
        #pragma unroll
        for (int rr = 0; rr < 2; rr++) {
            int row = by*BM + wm + mi*16 + rr*8 + g;
            int go  = gather_off(row);
            #pragma unroll
            for (int ni = 0; ni < 4; ni++) {
                int col = bx*BN + wn + ni*8 + 2*tig;
                float vx = acc[mi][ni][rr*2 + 0] + bias[col]
                         + extra[(long)row*DM + col];
                float vy = acc[mi][ni][rr*2 + 1] + bias[col + 1]
                         + extra[(long)row*DM + col + 1];
                float2 r = {vx, vy};
                *(float2*)&Cf[go + col] = r;
            }
        }
    }
}

// ---------------- bf16 tensor-core attention (head-major out) -------------------
__global__ void __launch_bounds__(256, 4)
attn_bf16_kernel(const bf16* __restrict__ qkv,
                 const float* __restrict__ logit_scale,
                 const float* __restrict__ rpb,
                 bf16* __restrict__ out)
{
    __shared__ __align__(16) bf16 Qs[TT*24];
    __shared__ __align__(16) bf16 Ks[TT*24];
    __shared__ __align__(16) bf16 Vs[TT*24];
    __shared__ float bs[NBIAS + 1];

    const int seq = blockIdx.x, h = blockIdx.y;
    const int t    = threadIdx.x;
    const int lane = t & 31, w = t >> 5;
    const int g    = lane >> 2, tig = lane & 3;

    for (int i = t; i < NBIAS; i += 256) bs[i] = rpb[h*NBIAS + i] * LOG2E;

    const long idx = ((long)h*NTOK + seq*TT + t) * HD;
    const float scale = __expf(fminf(logit_scale[h], 4.6051701859880914f));

    {
        uint4 qu0 = *(const uint4*)(qkv + idx);
        uint4 qu1 = *(const uint4*)(qkv + idx + 8);
        uint4 ku0 = *(const uint4*)(qkv + PART + idx);
        uint4 ku1 = *(const uint4*)(qkv + PART + idx + 8);
        uint4 vu0 = *(const uint4*)(qkv + 2L*PART + idx);
        uint4 vu1 = *(const uint4*)(qkv + 2L*PART + idx + 8);

        uint32_t uq[8] = {qu0.x,qu0.y,qu0.z,qu0.w, qu1.x,qu1.y,qu1.z,qu1.w};
        uint32_t uk[8] = {ku0.x,ku0.y,ku0.z,ku0.w, ku1.x,ku1.y,ku1.z,ku1.w};
        float q[16], k[16];
        float qs = 0.f, ks = 0.f;
        #pragma unroll
        for (int j = 0; j < 8; j++) {
            float2 fq = unpk(uq[j]), fk = unpk(uk[j]);
            q[2*j] = fq.x; q[2*j+1] = fq.y;
            k[2*j] = fk.x; k[2*j+1] = fk.y;
            qs += fq.x*fq.x + fq.y*fq.y;
            ks += fk.x*fk.x + fk.y*fk.y;
        }
        float qf = scale * 0.25f * LOG2E / fmaxf(sqrtf(qs), 1e-12f);
        float kf = 1.0f / fmaxf(sqrtf(ks), 1e-12f);
        uint32_t wq[8], wk[8];
        #pragma unroll
        for (int j = 0; j < 8; j++) {
            wq[j] = packbf(q[2*j]*qf, q[2*j+1]*qf);
            wk[j] = packbf(k[2*j]*kf, k[2*j+1]*kf);
        }
        *(uint4*)&Qs[t*24]     = make_uint4(wq[0],wq[1],wq[2],wq[3]);
        *(uint4*)&Qs[t*24 + 8] = make_uint4(wq[4],wq[5],wq[6],wq[7]);
        *(uint4*)&Ks[t*24]     = make_uint4(wk[0],wk[1],wk[2],wk[3]);
        *(uint4*)&Ks[t*24 + 8] = make_uint4(wk[4],wk[5],wk[6],wk[7]);
        *(uint4*)&Vs[t*24]      = vu0;
        *(uint4*)&Vs[t*24 + 8]  = vu1;
        *(uint4*)&Vs[t*24 + 16] = make_uint4(0x00003F80u, 0u, 0u, 0u);  // ones col
    }
    __syncthreads();

    uint32_t sQ = (uint32_t)__cvta_generic_to_shared(Qs);
    uint32_t sK = (uint32_t)__cvta_generic_to_shared(Ks);
    uint32_t sV = (uint32_t)__cvta_generic_to_shared(Vs);

    const int m0 = w * 32;
    const int fr = (lane & 7) + ((lane >> 3) & 1) * 8;
    const int fc = (lane >> 4) * 8;

    uint32_t qa[2][4];
    #pragma unroll
    for (int mi = 0; mi < 2; mi++)
        ldm_x4(qa[mi], sQ + 2*((m0 + mi*16 + fr)*24 + fc));

    float oacc[2][3][4] = {};

    #pragma unroll 1
    for (int cc = 0; cc < 8; cc++) {
        const int s0 = cc * 32;
        float sacc[2][4][4];

        #pragma unroll
        for (int mi = 0; mi < 2; mi++)
            #pragma unroll
            for (int ni = 0; ni < 4; ni++) {
                int d = m0 + mi*16 + g - (s0 + ni*8 + 2*tig) + (MAXT-1);
                sacc[mi][ni][0] = bs[d];
                sacc[mi][ni][1] = bs[d-1];
                sacc[mi][ni][2] = bs[d+8];
                sacc[mi][ni][3] = bs[d+7];
            }

        #pragma unroll
        for (int ni = 0; ni < 4; ni++) {
            uint32_t kb[2];
            ldm_x2(kb, sK + 2*((s0 + ni*8 + (lane & 7))*24 + ((lane >> 3) & 1)*8));
            #pragma unroll
            for (int mi = 0; mi < 2; mi++)
                mma16(sacc[mi][ni], qa[mi], kb);
        }

        #pragma unroll
        for (int mi = 0; mi < 2; mi++)
            #pragma unroll
            for (int ni = 0; ni < 4; ni++) {
                sacc[mi][ni][0] = ex2(sacc[mi][ni][0]);
                sacc[mi][ni][1] = ex2(sacc[mi][ni][1]);
                sacc[mi][ni][2] = ex2(sacc[mi][ni][2]);
                sacc[mi][ni][3] = ex2(sacc[mi][ni][3]);
            }

        #pragma unroll
        for (int kk = 0; kk < 2; kk++) {
            uint32_t pa[2][4];
            #pragma unroll
            for (int mi = 0; mi < 2; mi++) {
                pa[mi][0] = packbf(sacc[mi][2*kk  ][0], sacc[mi][2*kk  ][1]);
                pa[mi][1] = packbf(sacc[mi][2*kk  ][2], sacc[mi][2*kk  ][3]);
                pa[mi][2] = packbf(sacc[mi][2*kk+1][0], sacc[mi][2*kk+1][1]);
                pa[mi][3] = packbf(sacc[mi][2*kk+1][2], sacc[mi][2*kk+1][3]);
            }
            #pragma unroll
            for (int nd = 0; nd < 3; nd++) {
                uint32_t vb[2];
                ldm_x2_t(vb, sV + 2*((s0 + kk*16 + (lane & 15))*24 + nd*8));
                #pragma unroll
                for (int mi = 0; mi < 2; mi++)
                    mma16(oacc[mi][nd], pa[mi], vb);
            }
        }
    }

    #pragma unroll
    for (int mi = 0; mi < 2; mi++) {
        #pragma unroll
        for (int rr = 0; rr < 2; rr++) {
            float l = __shfl_sync(0xffffffffu, oacc[mi][2][rr*2], lane & ~3);
            float il = 1.0f / l;
            int row = m0 + mi*16 + rr*8 + g;
            long oidx = ((long)h*NTOK + seq*TT + row) * HD;
            #pragma unroll
            for (int nd = 0; nd < 2; nd++) {
                *(uint32_t*)&out[oidx + nd*8 + 2*tig] =
                    packbf(oacc[mi][nd][rr*2+0]*il, oacc[mi][nd][rr*2+1]*il);
            }
        }
    }
}

// -------------------------------- launch ----------------------------------------
extern "C" void kernel_launch(void* const* d_in, const int* in_sizes, int n_in,
                              void* d_out, int out_size)
{
    const float* x     = (const float*)d_in[0];
    const float* ln1g  = (const float*)d_in[1];
    const float* ln1b  = (const float*)d_in[2];
    const float* qkvw  = (const float*)d_in[3];
    const float* qkvb  = (const float*)d_in[4];
    const float* projw = (const float*)d_in[5];
    const float* projb = (const float*)d_in[6];
    const float* ls    = (const float*)d_in[7];
    const float* rpb   = (const float*)d_in[8];
    const float* ln2g  = (const float*)d_in[9];
    const float* ln2b  = (const float*)d_in[10];
    const float* w1    = (const float*)d_in[11];
    const float* b1    = (const float*)d_in[12];
    const float* w2    = (const float*)d_in[13];
    const float* b2    = (const float*)d_in[14];
    float* out = (float*)d_out;

    bf16 *xn, *qkv, *attn, *z, *hb, *wbuf;
    float *xf;
    cudaGetSymbolAddress((void**)&xn,   g_xn);
    cudaGetSymbolAddress((void**)&qkv,  g_qkv);
    cudaGetSymbolAddress((void**)&attn, g_attn);
    cudaGetSymbolAddress((void**)&xf,   g_xf);
    cudaGetSymbolAddress((void**)&z,    g_z);
    cudaGetSymbolAddress((void**)&hb,   g_h);
    cudaGetSymbolAddress((void**)&wbuf, g_w);

    cudaFuncSetAttribute(mp_gemm<3, 4>, cudaFuncAttributeMaxDynamicSharedMemorySize, MP_SMEM);
    cudaFuncSetAttribute(mp_gemm<4, 2>, cudaFuncAttributeMaxDynamicSharedMemorySize, MP_SMEM);
    cudaFuncSetAttribute(mma_gemm<128, 128, 1, 1>, cudaFuncAttributeMaxDynamicSharedMemorySize, GEMM_SMEM);
    cudaFuncSetAttribute(mma_gemm<512, 128, 3, 0>, cudaFuncAttributeMaxDynamicSharedMemorySize, GEMM_SMEM);

    // 0+1) LN1 (gather) + weight prep in one launch
    ln1w_kernel<<<LNBLKS + WBLKS, 256>>>(x, ln1g, ln1b, xn,
                                         qkvw, projw, w1, w2, wbuf);
    // 2) QKV projection (fixed A, 3 N-passes) -> head-major bf16 q/k/v
    mp_gemm<3, 4><<<NTOK/BM, 256, MP_SMEM>>>(xn, wbuf + WOFF_QKV, qkvb, qkv);
    // 3) bf16 tensor-core attention -> head-major attn
    attn_bf16_kernel<<<dim3(SEQS, HH), 256>>>(qkv, ls, rpb, attn);
    // 4) proj + residual -> xf (fp32), fused LN2 -> z (bf16)
    mma_gemm<128, 128, 1, 1><<<dim3(1, NTOK/BM), 256, GEMM_SMEM>>>(
        attn, wbuf + WOFF_PROJ, projb, x, xf, z, ln2g, ln2b);
    // 5) FFN1 + exact GELU (fixed A, 4 N-passes) -> h (bf16)
    mp_gemm<4, 2><<<NTOK/BM, 256, MP_SMEM>>>(z, wbuf + WOFF_W1, b1, hb);
    // 6) FFN2 + residual -> scatter fp32 (B,T,V,D) output
    mma_gemm<512, 128, 3, 0><<<dim3(1, NTOK/BM), 256, GEMM_SMEM>>>(
        hb, wbuf + WOFF_W2, b2, xf, out, nullptr, nullptr, nullptr);
}

// round 17
// speedup vs baseline: 1.0558x; 1.0073x over previous
#include <cuda_runtime.h>
#include <cuda_bf16.h>
#include <math.h>
#include <stdint.h>

// Problem constants
#define BB   16
#define TT   256
#define VV   25
#define DM   128
#define HH   8
#define HD   16
#define MAXT 300
#define SEQS (BB*VV)          // 400
#define NTOK (SEQS*TT)        // 102400
#define NBIAS (2*MAXT-1)      // 599
#define PART (HH*NTOK*HD)     // per q/k/v head-major part size (elements)
#define LOG2E 1.4426950408889634f

// GEMM tiling (bf16) — round-8 proven configuration
#define BM 128
#define BN 128
#define BK 32
#define NSTG 4
#define ASTR 40               // A row stride in halves
#define BSTR (BN + 8)         // 136 halves
#define SA (BM*ASTR)
#define SB (BK*BSTR)
#define STG (SA + SB)
#define GEMM_SMEM (NSTG*STG*2)  // 75776 bytes

// multi-pass GEMM (fixed A, streamed B)
#define MAF 136                 // fixed A row stride (halves)
#define MAFSZ (BM*MAF)          // 17408 halves
#define MSB (BK*136)            // 4352 halves per B stage
#define MP_SMEM ((MAFSZ + 4*MSB)*2)   // 69632 bytes

// weight-prep segment offsets (bf16 copies)
#define WOFF_QKV  0
#define WOFF_PROJ 49152
#define WOFF_W1   65536
#define WOFF_W2   131072
#define WTOTAL    196608
#define LNBLKS (NTOK/8)       // 12800 LN blocks
#define WBLKS  (WTOTAL/256)   // 768 wprep blocks

typedef __nv_bfloat16 bf16;

// ---------------- scratch (device globals; no runtime allocation) -------------
__device__ bf16  g_xn  [NTOK*DM];     // LN1 output
__device__ bf16  g_qkv [NTOK*3*DM];   // q/k/v, head-major [3][H][NTOK][16]
__device__ bf16  g_attn[NTOK*DM];     // attention output, head-major
__device__ float g_xf  [NTOK*DM];     // after proj + residual (fp32)
__device__ bf16  g_z   [NTOK*DM];     // LN2 output
__device__ bf16  g_h   [NTOK*4*DM];   // FFN hidden
__device__ bf16  g_w   [WTOTAL];      // bf16 weights

// ---------------- helpers ------------------------------------------------------
__device__ __forceinline__ uint32_t packbf(float lo, float hi) {
    uint32_t r;
    asm("cvt.rn.bf16x2.f32 %0, %1, %2;" : "=r"(r) : "f"(hi), "f"(lo));
    return r;
}
__device__ __forceinline__ float2 unpk(uint32_t u) {
    __nv_bfloat162 h = *reinterpret_cast<__nv_bfloat162*>(&u);
    return make_float2(__bfloat162float(h.x), __bfloat162float(h.y));
}
__device__ __forceinline__ float ex2(float x) {
    float r;
    asm("ex2.approx.ftz.f32 %0, %1;" : "=f"(r) : "f"(x));
    return r;
}
__device__ __forceinline__ void mma16(float* c, const uint32_t* a, const uint32_t* b) {
    asm volatile(
        "mma.sync.aligned.m16n8k16.row.col.f32.bf16.bf16.f32 "
        "{%0,%1,%2,%3}, {%4,%5,%6,%7}, {%8,%9}, {%0,%1,%2,%3};"
        : "+f"(c[0]), "+f"(c[1]), "+f"(c[2]), "+f"(c[3])
        : "r"(a[0]), "r"(a[1]), "r"(a[2]), "r"(a[3]), "r"(b[0]), "r"(b[1]));
}
__device__ __forceinline__ void ldm_x4(uint32_t* r, uint32_t addr) {
    asm volatile("ldmatrix.sync.aligned.m8n8.x4.shared.b16 {%0,%1,%2,%3}, [%4];"
        : "=r"(r[0]), "=r"(r[1]), "=r"(r[2]), "=r"(r[3]) : "r"(addr));
}
__device__ __forceinline__ void ldm_x2(uint32_t* r, uint32_t addr) {
    asm volatile("ldmatrix.sync.aligned.m8n8.x2.shared.b16 {%0,%1}, [%2];"
        : "=r"(r[0]), "=r"(r[1]) : "r"(addr));
}
__device__ __forceinline__ void ldm_x2_t(uint32_t* r, uint32_t addr) {
    asm volatile("ldmatrix.sync.aligned.m8n8.x2.trans.shared.b16 {%0,%1}, [%2];"
        : "=r"(r[0]), "=r"(r[1]) : "r"(addr));
}
__device__ __forceinline__ void cp16(uint32_t dst, const void* src) {
    asm volatile("cp.async.cg.shared.global [%0], [%1], 16;" :: "r"(dst), "l"(src));
}
// L1-allocating variant for weight/B streams shared across co-resident CTAs
__device__ __forceinline__ void cp16_ca(uint32_t dst, const void* src) {
    asm volatile("cp.async.ca.shared.global [%0], [%1], 16;" :: "r"(dst), "l"(src));
}
__device__ __forceinline__ void cp_commit() {
    asm volatile("cp.async.commit_group;" ::: "memory");
}
template<int N>
__device__ __forceinline__ void cp_wait() {
    asm volatile("cp.async.wait_group %0;" :: "n"(N) : "memory");
}
__device__ __forceinline__ int gather_off(int row) {
    int seq = row / TT, t = row % TT;
    int b = seq / VV, v = seq % VV;
    return ((b*TT + t)*VV + v) * DM;
}

// ---------------- LN1 (gather) + weight prep, one launch ------------------------
__global__ void ln1w_kernel(const float* __restrict__ in,
                            const float* __restrict__ gw,
                            const float* __restrict__ bw,
                            bf16* __restrict__ out,
                            const float* __restrict__ qkvw,
                            const float* __restrict__ projw,
                            const float* __restrict__ w1,
                            const float* __restrict__ w2,
                            bf16* __restrict__ wdst)
{
    if (blockIdx.x >= LNBLKS) {
        int i = (blockIdx.x - LNBLKS) * 256 + threadIdx.x;
        float v;
        if      (i < WOFF_PROJ) v = qkvw[i];
        else if (i < WOFF_W1)   v = projw[i - WOFF_PROJ];
        else if (i < WOFF_W2)   v = w1[i - WOFF_W1];
        else                    v = w2[i - WOFF_W2];
        wdst[i] = __float2bfloat16(v);
        return;
    }

    int m    = (blockIdx.x * blockDim.x + threadIdx.x) >> 5;
    int lane = threadIdx.x & 31;
    int seq = m / TT, t = m % TT;
    int b = seq / VV, v = seq % VV;
    const float* src = in + ((b*TT + t)*VV + v) * DM;

    float4 x = *(const float4*)(src + lane*4);
    float s = x.x + x.y + x.z + x.w;
    #pragma unroll
    for (int o = 16; o > 0; o >>= 1) s += __shfl_xor_sync(0xffffffffu, s, o);
    float mean = s * (1.0f / DM);

    float dx0 = x.x - mean, dx1 = x.y - mean, dx2 = x.z - mean, dx3 = x.w - mean;
    float q = dx0*dx0 + dx1*dx1 + dx2*dx2 + dx3*dx3;
    #pragma unroll
    for (int o = 16; o > 0; o >>= 1) q += __shfl_xor_sync(0xffffffffu, q, o);
    float inv = rsqrtf(q * (1.0f / DM) + 1e-5f);

    float4 gv = *(const float4*)(gw + lane*4);
    float4 bv = *(const float4*)(bw + lane*4);
    uint2 r;
    r.x = packbf(dx0*inv*gv.x + bv.x, dx1*inv*gv.y + bv.y);
    r.y = packbf(dx2*inv*gv.z + bv.z, dx3*inv*gv.w + bv.w);
    *(uint2*)(out + (long)m*DM + lane*4) = r;
}

// ---------------- multi-pass GEMM: fixed A (K=128 resident), streamed B ---------
// EPI 2: gelu(+bias) -> Cb[row*NDIM+col]          (FFN1, NPASS=4)
// EPI 4: +bias -> head-major q/k/v scatter        (QKV,  NPASS=3)
template<int NPASS, int EPI>
__global__ void __launch_bounds__(256, 2)
mp_gemm(const bf16* __restrict__ A,
        const bf16* __restrict__ B,
        const float* __restrict__ bias,
        bf16* __restrict__ Cb)
{
    extern __shared__ bf16 sm[];
    uint32_t sb = (uint32_t)__cvta_generic_to_shared(sm);

    const int tid  = threadIdx.x;
    const int by   = blockIdx.x;
    const int lane = tid & 31, warp = tid >> 5;
    const int wm   = (warp & 1) * 64;
    const int wn   = (warp >> 1) * 32;
    const int g    = lane >> 2, tig = lane & 3;
    const int NDIM = NPASS * BN;
    const int NT   = 4 * NPASS;

    auto loadB = [&](int tt) {
        int pass = tt >> 2, kt = tt & 3, slot = tt & 3;
        #pragma unroll
        for (int j = 0; j < 2; j++) {
            int id = tid + j*256;
            int r = id >> 4, c8 = (id & 15) * 8;
            cp16_ca(sb + 2*(MAFSZ + slot*MSB + r*136 + c8),
                    B + (long)(kt*BK + r)*NDIM + pass*BN + c8);
        }
    };

    // prologue: A (full 128x128) + B0 in group 0, then B1, B2
    #pragma unroll
    for (int i = 0; i < 8; i++) {
        int id = tid + i*256;
        int r = id >> 4, c8 = (id & 15) * 8;
        cp16(sb + 2*(r*MAF + c8), A + (long)(by*BM + r)*DM + c8);
    }
    loadB(0); cp_commit();
    loadB(1); cp_commit();
    loadB(2); cp_commit();

    const int a_roff = (lane & 7) + ((lane >> 3) & 1) * 8;
    const int a_coff = (lane >> 4) * 8;
    const int b_roff = lane & 15;

    float acc[4][4][4];

    #pragma unroll 1
    for (int tt = 0; tt < NT; tt++) {
        cp_wait<2>();
        __syncthreads();
        if (tt + 3 < NT) loadB(tt + 3);
        cp_commit();                 // unconditional: exact group counting

        const int pass = tt >> 2, kt = tt & 3, slot = tt & 3;
        if (kt == 0) {
            #pragma unroll
            for (int mi = 0; mi < 4; mi++)
                #pragma unroll
                for (int ni = 0; ni < 4; ni++)
                    #pragma unroll
                    for (int e = 0; e < 4; e++) acc[mi][ni][e] = 0.f;
        }

        uint32_t bbase = sb + 2*(MAFSZ + slot*MSB);
        #pragma unroll
        for (int ks = 0; ks < 2; ks++) {
            uint32_t af[4][4], bf[4][2];
            #pragma unroll
            for (int mi = 0; mi < 4; mi++)
                ldm_x4(af[mi], sb + 2*((wm + mi*16 + a_roff)*MAF
                                       + kt*BK + ks*16 + a_coff));
            #pragma unroll
            for (int ni = 0; ni < 4; ni++)
                ldm_x2_t(bf[ni], bbase + 2*((ks*16 + b_roff)*136 + wn + ni*8));
            #pragma unroll
            for (int mi = 0; mi < 4; mi++)
                #pragma unroll
                for (int ni = 0; ni < 4; ni++)
                    mma16(acc[mi][ni], af[mi], bf[ni]);
        }

        if (kt == 3) {
            #pragma unroll
            for (int mi = 0; mi < 4; mi++) {
                #pragma unroll
                for (int rr = 0; rr < 2; rr++) {
                    int row = by*BM + wm + mi*16 + rr*8 + g;
                    #pragma unroll
                    for (int ni = 0; ni < 4; ni++) {
                        int col = pass*BN + wn + ni*8 + 2*tig;
                        float vx = acc[mi][ni][rr*2 + 0] + bias[col];
                        float vy = acc[mi][ni][rr*2 + 1] + bias[col + 1];
                        if (EPI == 2) {
                            vx = 0.5f * vx * (1.0f + erff(vx * 0.70710678118654752f));
                            vy = 0.5f * vy * (1.0f + erff(vy * 0.70710678118654752f));
                            *(uint32_t*)&Cb[(long)row*NDIM + col] = packbf(vx, vy);
                        } else {   // EPI 4: head-major q/k/v
                            int part = col >> 7, rem = col & 127;
                            int hh = rem >> 4, d = rem & 15;
                            *(uint32_t*)&Cb[(long)part*PART
                                            + ((long)hh*NTOK + row)*HD + d] =
                                packbf(vx, vy);
                        }
                    }
                }
            }
        }
    }
}

// ---------------- bf16 tensor-core GEMM (round-8 proven; proj & FFN2) -----------
// EPI 1: + bias + gather(x) -> xf (Cf fp32); fused LayerNorm -> z (Cb bf16)
// EPI 3: + bias + extra[row] -> scatter fp32 out  (FFN2)
// AG 1: A is head-major [H][NTOK][16] bf16
template<int KDIM, int NDIM, int EPI, int AG>
__global__ void __launch_bounds__(256, 2)
mma_gemm(const bf16* __restrict__ A,
         const bf16* __restrict__ B,
         const float* __restrict__ bias,
         const float* __restrict__ extra,
         float* __restrict__ Cf,
         bf16* __restrict__ Cb,
         const float* __restrict__ lng,
         const float* __restrict__ lnb)
{
    extern __shared__ bf16 smem[];
    uint32_t sbase = (uint32_t)__cvta_generic_to_shared(smem);

    const int tid  = threadIdx.x;
    const int bx   = blockIdx.x, by = blockIdx.y;
    const int lane = tid & 31, warp = tid >> 5;
    const int wm   = (warp & 1) * 64;
    const int wn   = (warp >> 1) * 32;
    const int g    = lane >> 2, tig = lane & 3;

    const int NK = KDIM / BK;
    float acc[4][4][4] = {};

    auto load_tile = [&](int kt, int slot) {
        uint32_t sb = sbase + 2*(slot*STG);
        #pragma unroll
        for (int i = 0; i < 2; i++) {
            int id = tid + i*256;
            int r = id >> 2, c8 = (id & 3) * 8;
            uint32_t dst = sb + 2*(r*ASTR + c8);
            int row = by*BM + r;
            if (AG) {
                int k = kt*BK + c8;
                cp16(dst, A + ((long)((k >> 4)*NTOK + row))*HD + (k & 15));
            } else {
                cp16(dst, A + (long)row*KDIM + kt*BK + c8);
            }
        }
        #pragma unroll
        for (int j = 0; j < 2; j++) {
            int id = tid + j*256;
            int r = id >> 4, c8 = (id & 15) * 8;
            uint32_t dst = sb + 2*(SA + r*BSTR + c8);
            cp16_ca(dst, B + (long)(kt*BK + r)*NDIM + bx*BN + c8);
        }
    };

    #pragma unroll
    for (int s = 0; s < NSTG-1; s++) {
        if (s < NK) load_tile(s, s);
        cp_commit();
    }

    const int a_roff = (lane & 7) + ((lane >> 3) & 1) * 8;
    const int a_coff = (lane >> 4) * 8;
    const int b_roff = lane & 15;

    #pragma unroll 1
    for (int kt = 0; kt < NK; kt++) {
        cp_wait<NSTG-2>();
        __syncthreads();
        int lt = kt + NSTG - 1;
        if (lt < NK) load_tile(lt, lt & (NSTG-1));
        cp_commit();

        uint32_t abase = sbase + 2*((kt & (NSTG-1))*STG);
        uint32_t bbase = abase + 2*SA;

        #pragma unroll
        for (int ks = 0; ks < 2; ks++) {
            uint32_t af[4][4], bf[4][2];
            #pragma unroll
            for (int mi = 0; mi < 4; mi++)
                ldm_x4(af[mi], abase + 2*((wm + mi*16 + a_roff)*ASTR + ks*16 + a_coff));
            #pragma unroll
            for (int ni = 0; ni < 4; ni++)
                ldm_x2_t(bf[ni], bbase + 2*((ks*16 + b_roff)*BSTR + wn + ni*8));
            #pragma unroll
            for (int mi = 0; mi < 4; mi++)
                #pragma unroll
                for (int ni = 0; ni < 4; ni++)
                    mma16(acc[mi][ni], af[mi], bf[ni]);
        }
    }

    // ---------------- epilogue ----------------
    if (EPI == 1) {
        __syncthreads();
        float* red = (float*)smem;
        const int wngrp = warp >> 1;

        float rsum[4][2], rsq[4][2];
        #pragma unroll
        for (int mi = 0; mi < 4; mi++) {
            #pragma unroll
            for (int rr = 0; rr < 2; rr++) {
                int rloc = wm + mi*16 + rr*8 + g;
                int row  = by*BM + rloc;
                int go   = gather_off(row);
                float ls = 0.f, lq = 0.f;
                #pragma unroll
                for (int ni = 0; ni < 4; ni++) {
                    int col = wn + ni*8 + 2*tig;
                    float vx = acc[mi][ni][rr*2+0] + bias[col]   + extra[go + col];
                    float vy = acc[mi][ni][rr*2+1] + bias[col+1] + extra[go + col + 1];
                    acc[mi][ni][rr*2+0] = vx;
                    acc[mi][ni][rr*2+1] = vy;
                    float2 r = {vx, vy};
                    *(float2*)&Cf[(long)row*DM + col] = r;
                    ls += vx + vy;
                    lq += vx*vx + vy*vy;
                }
                rsum[mi][rr] = ls; rsq[mi][rr] = lq;
            }
        }
        #pragma unroll
        for (int mi = 0; mi < 4; mi++)
            #pragma unroll
            for (int rr = 0; rr < 2; rr++) {
                #pragma unroll
                for (int o = 1; o <= 2; o <<= 1) {
                    rsum[mi][rr] += __shfl_xor_sync(0xffffffffu, rsum[mi][rr], o);
                    rsq[mi][rr]  += __shfl_xor_sync(0xffffffffu, rsq[mi][rr],  o);
                }
            }
        if (tig == 0) {
            #pragma unroll
            for (int mi = 0; mi < 4; mi++)
                #pragma unroll
                for (int rr = 0; rr < 2; rr++) {
                    int rloc = wm + mi*16 + rr*8 + g;
                    red[(rloc*4 + wngrp)*2 + 0] = rsum[mi][rr];
                    red[(rloc*4 + wngrp)*2 + 1] = rsq[mi][rr];
                }
        }
        __syncthreads();
        #pragma unroll
        for (int mi = 0; mi < 4; mi++) {
            #pragma unroll
            for (int rr = 0; rr < 2; rr++) {
                int rloc = wm + mi*16 + rr*8 + g;
                int row  = by*BM + rloc;
                float s = 0.f, q = 0.f;
                #pragma unroll
                for (int w2 = 0; w2 < 4; w2++) {
                    s += red[(rloc*4 + w2)*2 + 0];
                    q += red[(rloc*4 + w2)*2 + 1];
                }
                float mean = s * (1.0f/DM);
                float var  = q * (1.0f/DM) - mean*mean;
                float inv  = rsqrtf(var + 1e-5f);
                #pragma unroll
                for (int ni = 0; ni < 4; ni++) {
                    int col = wn + ni*8 + 2*tig;
                    float zx = (acc[mi][ni][rr*2+0] - mean)*inv*lng[col]   + lnb[col];
                    float zy = (acc[mi][ni][rr*2+1] - mean)*inv*lng[col+1] + lnb[col+1];
                    *(uint32_t*)&Cb[(long)row*DM + col] = packbf(zx, zy);
                }
            }
        }
        return;
    }

    // EPI 3
    #pragma unroll
    for (int mi = 0; mi < 4; mi++) {
        #pragma unroll
        for (int rr = 0; rr < 2; rr++) {
            int row = by*BM + wm + mi*16 + rr*8 + g;
            int go  = gather_off(row);
            #pragma unroll
            for (int ni = 0; ni < 4; ni++) {
                int col = bx*BN + wn + ni*8 + 2*tig;
                float vx = acc[mi][ni][rr*2 + 0] + bias[col]
                         + extra[(long)row*DM + col];
                float vy = acc[mi][ni][rr*2 + 1] + bias[col + 1]
                         + extra[(long)row*DM + col + 1];
                float2 r = {vx, vy};
                *(float2*)&Cf[go + col] = r;
            }
        }
    }
}

// ---------------- bf16 tensor-core attention (head-major out) -------------------
__global__ void __launch_bounds__(256, 4)
attn_bf16_kernel(const bf16* __restrict__ qkv,
                 const float* __restrict__ logit_scale,
                 const float* __restrict__ rpb,
                 bf16* __restrict__ out)
{
    __shared__ __align__(16) bf16 Qs[TT*24];
    __shared__ __align__(16) bf16 Ks[TT*24];
    __shared__ __align__(16) bf16 Vs[TT*24];
    __shared__ float bs[NBIAS + 1];

    const int seq = blockIdx.x, h = blockIdx.y;
    const int t    = threadIdx.x;
    const int lane = t & 31, w = t >> 5;
    const int g    = lane >> 2, tig = lane & 3;

    for (int i = t; i < NBIAS; i += 256) bs[i] = rpb[h*NBIAS + i] * LOG2E;

    const long idx = ((long)h*NTOK + seq*TT + t) * HD;
    const float scale = __expf(fminf(logit_scale[h], 4.6051701859880914f));

    {
        uint4 qu0 = *(const uint4*)(qkv + idx);
        uint4 qu1 = *(const uint4*)(qkv + idx + 8);
        uint4 ku0 = *(const uint4*)(qkv + PART + idx);
        uint4 ku1 = *(const uint4*)(qkv + PART + idx + 8);
        uint4 vu0 = *(const uint4*)(qkv + 2L*PART + idx);
        uint4 vu1 = *(const uint4*)(qkv + 2L*PART + idx + 8);

        uint32_t uq[8] = {qu0.x,qu0.y,qu0.z,qu0.w, qu1.x,qu1.y,qu1.z,qu1.w};
        uint32_t uk[8] = {ku0.x,ku0.y,ku0.z,ku0.w, ku1.x,ku1.y,ku1.z,ku1.w};
        float q[16], k[16];
        float qs = 0.f, ks = 0.f;
        #pragma unroll
        for (int j = 0; j < 8; j++) {
            float2 fq = unpk(uq[j]), fk = unpk(uk[j]);
            q[2*j] = fq.x; q[2*j+1] = fq.y;
            k[2*j] = fk.x; k[2*j+1] = fk.y;
            qs += fq.x*fq.x + fq.y*fq.y;
            ks += fk.x*fk.x + fk.y*fk.y;
        }
        float qf = scale * 0.25f * LOG2E / fmaxf(sqrtf(qs), 1e-12f);
        float kf = 1.0f / fmaxf(sqrtf(ks), 1e-12f);
        uint32_t wq[8], wk[8];
        #pragma unroll
        for (int j = 0; j < 8; j++) {
            wq[j] = packbf(q[2*j]*qf, q[2*j+1]*qf);
            wk[j] = packbf(k[2*j]*kf, k[2*j+1]*kf);
        }
        *(uint4*)&Qs[t*24]     = make_uint4(wq[0],wq[1],wq[2],wq[3]);
        *(uint4*)&Qs[t*24 + 8] = make_uint4(wq[4],wq[5],wq[6],wq[7]);
        *(uint4*)&Ks[t*24]     = make_uint4(wk[0],wk[1],wk[2],wk[3]);
        *(uint4*)&Ks[t*24 + 8] = make_uint4(wk[4],wk[5],wk[6],wk[7]);
        *(uint4*)&Vs[t*24]      = vu0;
        *(uint4*)&Vs[t*24 + 8]  = vu1;
        *(uint4*)&Vs[t*24 + 16] = make_uint4(0x00003F80u, 0u, 0u, 0u);  // ones col
    }
    __syncthreads();

    uint32_t sQ = (uint32_t)__cvta_generic_to_shared(Qs);
    uint32_t sK = (uint32_t)__cvta_generic_to_shared(Ks);
    uint32_t sV = (uint32_t)__cvta_generic_to_shared(Vs);

    const int m0 = w * 32;
    const int fr = (lane & 7) + ((lane >> 3) & 1) * 8;
    const int fc = (lane >> 4) * 8;

    uint32_t qa[2][4];
    #pragma unroll
    for (int mi = 0; mi < 2; mi++)
        ldm_x4(qa[mi], sQ + 2*((m0 + mi*16 + fr)*24 + fc));

    float oacc[2][3][4] = {};

    #pragma unroll 1
    for (int cc = 0; cc < 8; cc++) {
        const int s0 = cc * 32;
        float sacc[2][4][4];

        #pragma unroll
        for (int mi = 0; mi < 2; mi++)
            #pragma unroll
            for (int ni = 0; ni < 4; ni++) {
                int d = m0 + mi*16 + g - (s0 + ni*8 + 2*tig) + (MAXT-1);
                sacc[mi][ni][0] = bs[d];
                sacc[mi][ni][1] = bs[d-1];
                sacc[mi][ni][2] = bs[d+8];
                sacc[mi][ni][3] = bs[d+7];
            }

        #pragma unroll
        for (int ni = 0; ni < 4; ni++) {
            uint32_t kb[2];
            ldm_x2(kb, sK + 2*((s0 + ni*8 + (lane & 7))*24 + ((lane >> 3) & 1)*8));
            #pragma unroll
            for (int mi = 0; mi < 2; mi++)
                mma16(sacc[mi][ni], qa[mi], kb);
        }

        #pragma unroll
        for (int mi = 0; mi < 2; mi++)
            #pragma unroll
            for (int ni = 0; ni < 4; ni++) {
                sacc[mi][ni][0] = ex2(sacc[mi][ni][0]);
                sacc[mi][ni][1] = ex2(sacc[mi][ni][1]);
                sacc[mi][ni][2] = ex2(sacc[mi][ni][2]);
                sacc[mi][ni][3] = ex2(sacc[mi][ni][3]);
            }

        #pragma unroll
        for (int kk = 0; kk < 2; kk++) {
            uint32_t pa[2][4];
            #pragma unroll
            for (int mi = 0; mi < 2; mi++) {
                pa[mi][0] = packbf(sacc[mi][2*kk  ][0], sacc[mi][2*kk  ][1]);
                pa[mi][1] = packbf(sacc[mi][2*kk  ][2], sacc[mi][2*kk  ][3]);
                pa[mi][2] = packbf(sacc[mi][2*kk+1][0], sacc[mi][2*kk+1][1]);
                pa[mi][3] = packbf(sacc[mi][2*kk+1][2], sacc[mi][2*kk+1][3]);
            }
            #pragma unroll
            for (int nd = 0; nd < 3; nd++) {
                uint32_t vb[2];
                ldm_x2_t(vb, sV + 2*((s0 + kk*16 + (lane & 15))*24 + nd*8));
                #pragma unroll
                for (int mi = 0; mi < 2; mi++)
                    mma16(oacc[mi][nd], pa[mi], vb);
            }
        }
    }

    #pragma unroll
    for (int mi = 0; mi < 2; mi++) {
        #pragma unroll
        for (int rr = 0; rr < 2; rr++) {
            float l = __shfl_sync(0xffffffffu, oacc[mi][2][rr*2], lane & ~3);
            float il = 1.0f / l;
            int row = m0 + mi*16 + rr*8 + g;
            long oidx = ((long)h*NTOK + seq*TT + row) * HD;
            #pragma unroll
            for (int nd = 0; nd < 2; nd++) {
                *(uint32_t*)&out[oidx + nd*8 + 2*tig] =
                    packbf(oacc[mi][nd][rr*2+0]*il, oacc[mi][nd][rr*2+1]*il);
            }
        }
    }
}

// -------------------------------- launch ----------------------------------------
extern "C" void kernel_launch(void* const* d_in, const int* in_sizes, int n_in,
                              void* d_out, int out_size)
{
    const float* x     = (const float*)d_in[0];
    const float* ln1g  = (const float*)d_in[1];
    const float* ln1b  = (const float*)d_in[2];
    const float* qkvw  = (const float*)d_in[3];
    const float* qkvb  = (const float*)d_in[4];
    const float* projw = (const float*)d_in[5];
    const float* projb = (const float*)d_in[6];
    const float* ls    = (const float*)d_in[7];
    const float* rpb   = (const float*)d_in[8];
    const float* ln2g  = (const float*)d_in[9];
    const float* ln2b  = (const float*)d_in[10];
    const float* w1    = (const float*)d_in[11];
    const float* b1    = (const float*)d_in[12];
    const float* w2    = (const float*)d_in[13];
    const float* b2    = (const float*)d_in[14];
    float* out = (float*)d_out;

    bf16 *xn, *qkv, *attn, *z, *hb, *wbuf;
    float *xf;
    cudaGetSymbolAddress((void**)&xn,   g_xn);
    cudaGetSymbolAddress((void**)&qkv,  g_qkv);
    cudaGetSymbolAddress((void**)&attn, g_attn);
    cudaGetSymbolAddress((void**)&xf,   g_xf);
    cudaGetSymbolAddress((void**)&z,    g_z);
    cudaGetSymbolAddress((void**)&hb,   g_h);
    cudaGetSymbolAddress((void**)&wbuf, g_w);

    cudaFuncSetAttribute(mp_gemm<3, 4>, cudaFuncAttributeMaxDynamicSharedMemorySize, MP_SMEM);
    cudaFuncSetAttribute(mp_gemm<4, 2>, cudaFuncAttributeMaxDynamicSharedMemorySize, MP_SMEM);
    cudaFuncSetAttribute(mma_gemm<128, 128, 1, 1>, cudaFuncAttributeMaxDynamicSharedMemorySize, GEMM_SMEM);
    cudaFuncSetAttribute(mma_gemm<512, 128, 3, 0>, cudaFuncAttributeMaxDynamicSharedMemorySize, GEMM_SMEM);

    // 0+1) LN1 (gather) + weight prep in one launch
    ln1w_kernel<<<LNBLKS + WBLKS, 256>>>(x, ln1g, ln1b, xn,
                                         qkvw, projw, w1, w2, wbuf);
    // 2) QKV projection (fixed A, 3 N-passes) -> head-major bf16 q/k/v
    mp_gemm<3, 4><<<NTOK/BM, 256, MP_SMEM>>>(xn, wbuf + WOFF_QKV, qkvb, qkv);
    // 3) bf16 tensor-core attention -> head-major attn
    attn_bf16_kernel<<<dim3(SEQS, HH), 256>>>(qkv, ls, rpb, attn);
    // 4) proj + residual -> xf (fp32), fused LN2 -> z (bf16)
    mma_gemm<128, 128, 1, 1><<<dim3(1, NTOK/BM), 256, GEMM_SMEM>>>(
        attn, wbuf + WOFF_PROJ, projb, x, xf, z, ln2g, ln2b);
    // 5) FFN1 + exact GELU (fixed A, 4 N-passes) -> h (bf16)
    mp_gemm<4, 2><<<NTOK/BM, 256, MP_SMEM>>>(z, wbuf + WOFF_W1, b1, hb);
    // 6) FFN2 + residual -> scatter fp32 (B,T,V,D) output
    mma_gemm<512, 128, 3, 0><<<dim3(1, NTOK/BM), 256, GEMM_SMEM>>>(
        hb, wbuf + WOFF_W2, b2, xf, out, nullptr, nullptr, nullptr);
}